// round 15
// baseline (speedup 1.0000x reference)
#include <cuda_runtime.h>
#include <cstdint>

// TreeAttention: N=8, T_DST=512, T_SRC=4096, HID=64, K=64, W0=64,
// SCALE_UP=2, OVERSAMPLE=1.5. One CTA (128 threads) per (n, a) row.
//
// Score caching: child0's gather index equals its parent's BIT-EXACTLY,
// so child0 scores AND gather indices are copied at placement; only dual
// children (and the initial 64 rows) are gathered via worklist wl.
// Exact-arithmetic specializations: it0..4 scale==2 (integer emission,
// no clamps); ratio_n = tsrc*2^-k exact; it5 scale = tsrc*2^-11 exact,
// ratio_n == 1. Only the reference's ws/tsrc division remains.
//
// Top-k membership select: LINEAR monotone bucketing (0.25-wide bins,
// clamp [0,255]) -> crossing bucket holds only ~2-4 candidates; exact
// in-bucket rank on full sortable keys. All 4 warps run the histogram
// suffix scan REDUNDANTLY and broadcast the crossing via ballot+shfl
// (no barrier between scan and candidate compaction).
//
// it6: final set = (top-64 ∪ {pixel 0}) truncated to 64 smallest pixels
// via ballot compaction. AV gather: float4 warp-cooperative.

#define NEGV  (-32000.0f)
#define FMINV (-1e30f)

__device__ __forceinline__ unsigned sortable_u(float f) {
    unsigned i = __float_as_uint(f);
    return i ^ ((unsigned)((int)i >> 31) | 0x80000000u);
}

__device__ __forceinline__ int lin_bucket(float s) {
    const int b = __float2int_rd(__fmaf_rn(s, 4.0f, 128.0f));
    return min(255, max(0, b));
}

__global__ __launch_bounds__(128, 10)
void tree_attn_kernel(const float* __restrict__ q,
                      const float* __restrict__ k,
                      const float* __restrict__ v,
                      float* __restrict__ out)
{
    const int row  = blockIdx.x;          // n*512 + a
    const int n    = row >> 9;
    const int a    = row & 511;
    const int t    = threadIdx.x;         // 0..127
    const int lane = t & 31;
    const int wid  = t >> 5;
    const int c8   = t & 7;               // chunk within row (8 threads/row)
    const int or8  = t >> 3;              // row slot (0..15)

    __shared__ __align__(16) float qs[64];
    __shared__ __align__(16) float sc[128];
    __shared__ __align__(16) float pr[64];
    __shared__ int      pix[128];
    __shared__ int      xs[128];          // gather indices
    __shared__ __align__(16) int hist[256];   // also reused as float4[64]
    __shared__ unsigned cand1[64];
    __shared__ unsigned cand2[64];
    __shared__ int      wl[128];          // uncached-slot worklist
    __shared__ int      wlcnt;
    __shared__ int      wsum[4];
    __shared__ float    fsum[4];
    __shared__ int      sel[3];           // cnt1, cnt2, extra

    const float  tsrc = (float)(3585 + a);        // T_SRC - T_DST + 1 + a
    const float* kb   = k + (size_t)n * (4096 * 64);

    if (t < 64) qs[t] = q[(size_t)row * 64 + t];
    {
        const float r0 = __fmul_rn(tsrc, 0.015625f);  // tsrc/64 exact
        const int   p  = (t < 96) ? t : 0;
        pix[t] = p;
        xs[t]  = min((int)rintf(__fmul_rn((float)p, r0)), 4095);
    }
    if (t < 64) wl[t] = t;                // initial rows all uncached
    if (t == 0) wlcnt = 64;
    __syncthreads();

    const float4 qa = ((const float4*)qs)[c8];
    const float4 qb = ((const float4*)qs)[c8 + 8];

    float ws = 64.0f;
    int   V  = 64;                        // valid prefix length (shared-state)

    #pragma unroll 1
    for (int it = 0; it < 6; ++it) {
        const int tks_max = (it == 0) ? 63 : 96;
        const int Zcur    = (it == 0) ? 96 : 128;

        // ---- A: gather ONLY uncached rows (worklist); zero hist ----
        const int U = wlcnt;              // read before any thread passes B1
        if (t >= V) sc[t] = NEGV;
        ((int2*)hist)[t] = make_int2(0, 0);
        if (t < 2) sel[t] = 0;
        #pragma unroll 1
        for (int base = 0; base < U; base += 32) {
            if (base + (wid << 2) < U) {  // warp-uniform: this warp has rows
                const int  i0 = base + or8;
                const int  i1 = base + 16 + or8;
                const bool v0 = (i0 < U);
                const bool v1 = (i1 < U);
                const int  r0 = v0 ? wl[i0] : 0;
                const int  r1 = v1 ? wl[i1] : 0;
                float acc0 = 0.0f, acc1 = 0.0f;
                if (v0) {
                    const float4* kr = (const float4*)(kb + (size_t)xs[r0] * 64);
                    const float4 A = __ldg(kr + c8);
                    const float4 B = __ldg(kr + c8 + 8);
                    acc0  = A.x*qa.x + A.y*qa.y + A.z*qa.z + A.w*qa.w;
                    acc0 += B.x*qb.x + B.y*qb.y + B.z*qb.z + B.w*qb.w;
                }
                if (v1) {
                    const float4* kr = (const float4*)(kb + (size_t)xs[r1] * 64);
                    const float4 A = __ldg(kr + c8);
                    const float4 B = __ldg(kr + c8 + 8);
                    acc1  = A.x*qa.x + A.y*qa.y + A.z*qa.z + A.w*qa.w;
                    acc1 += B.x*qb.x + B.y*qb.y + B.z*qb.z + B.w*qb.w;
                }
                acc0 += __shfl_xor_sync(0xFFFFFFFFu, acc0, 1);
                acc1 += __shfl_xor_sync(0xFFFFFFFFu, acc1, 1);
                acc0 += __shfl_xor_sync(0xFFFFFFFFu, acc0, 2);
                acc1 += __shfl_xor_sync(0xFFFFFFFFu, acc1, 2);
                acc0 += __shfl_xor_sync(0xFFFFFFFFu, acc0, 4);
                acc1 += __shfl_xor_sync(0xFFFFFFFFu, acc1, 4);
                if (v0 && c8 == 0) sc[r0] = acc0;
                if (v1 && c8 == 0) sc[r1] = acc1;
            }
        }
        __syncthreads();                                     // B1
        if (t == 0) wlcnt = 0;            // safe: all reads of wl/U done

        // uniform params (single remaining fdiv: reference's ws/tsrc)
        float tkf = rintf(__fmul_rn(__fmul_rn(__fdiv_rn(ws, tsrc), 64.0f), 1.5f));
        tkf = fminf(fmaxf(tkf, 1.0f), fminf(ws - 1.0f, (float)(Zcur - 1)));
        const int  k1     = min((int)tkf, tks_max);          // dual top-k
        const int  k2     = tks_max;                         // winner top-k
        const bool needK2 = (V > tks_max);
        const bool pow2it = (it < 5);
        const float wsn   = pow2it ? __fmul_rn(ws, 2.0f) : tsrc;
        const float ratio_n = pow2it
            ? __fmul_rn(tsrc, __uint_as_float((unsigned)(120 - it) << 23))
            : 1.0f;

        const bool     valid  = (t < V);
        const float    sv     = sc[t];
        const int      myx    = xs[t];    // inherited by child0 (bit-exact)
        const unsigned u      = valid ? sortable_u(sv) : 0u;
        const int      bucket = valid ? lin_bucket(sv) : 0;
        if (valid) atomicAdd(&hist[bucket], 1);
        __syncthreads();                                     // B2

        // ---- redundant per-warp suffix scan + crossing broadcast ----
        int b1, m1, b2 = -1, m2 = 0;
        {
            const int  base4 = 248 - (lane << 3);
            const int4 A4 = *(const int4*)&hist[base4];
            const int4 B4 = *(const int4*)&hist[base4 + 4];
            const int  s  = A4.x+A4.y+A4.z+A4.w + B4.x+B4.y+B4.z+B4.w;
            int incl0 = s;
            #pragma unroll
            for (int d = 1; d < 32; d <<= 1) {
                const int o = __shfl_up_sync(0xFFFFFFFFu, incl0, d);
                if (lane >= d) incl0 += o;
            }
            int run = incl0 - s;
            const int hh[8] = {B4.w, B4.z, B4.y, B4.x, A4.w, A4.z, A4.y, A4.x};
            bool f1 = false, f2 = false;
            int b1l = 0, m1l = 0, b2l = 0, m2l = 0;
            #pragma unroll
            for (int j = 0; j < 8; ++j) {
                const int b = 255 - ((lane << 3) + j);
                const int h = hh[j];
                if (run < k1 && run + h >= k1) { b1l = b; m1l = run; f1 = true; }
                if (needK2 && run < k2 && run + h >= k2) { b2l = b; m2l = run; f2 = true; }
                run += h;
            }
            const unsigned bb1 = __ballot_sync(0xFFFFFFFFu, f1);
            const int s1 = __ffs(bb1) - 1;
            b1 = __shfl_sync(0xFFFFFFFFu, b1l, s1);
            m1 = __shfl_sync(0xFFFFFFFFu, m1l, s1);
            if (needK2) {
                const unsigned bb2 = __ballot_sync(0xFFFFFFFFu, f2);
                const int s2 = __ffs(bb2) - 1;
                b2 = __shfl_sync(0xFFFFFFFFu, b2l, s2);
                m2 = __shfl_sync(0xFFFFFFFFu, m2l, s2);
            }
        }

        const bool c1 = valid && (bucket == b1);
        if (c1) cand1[atomicAdd(&sel[0], 1) & 63] = u;
        const bool c2 = needK2 && valid && (bucket == b2);
        if (c2) cand2[atomicAdd(&sel[1], 1) & 63] = u;
        __syncthreads();                                     // B4

        // ---- membership + monotone child emission ----
        bool winner = valid, dual = false;
        if (valid) {
            if (bucket > b1) dual = true;
            else if (c1) {
                const int C = min(sel[0], 64);
                int r = 0;
                for (int j = 0; j < C; ++j) r += (int)(cand1[j] > u);
                dual = (r < k1 - m1);
            }
            if (needK2) {
                if (bucket > b2) winner = true;
                else if (c2) {
                    const int C = min(sel[1], 64);
                    int r = 0;
                    for (int j = 0; j < C; ++j) r += (int)(cand2[j] > u);
                    winner = (r < k2 - m2);
                } else winner = false;
            }
        }
        int e = 0, p0 = 0;
        if (winner) {
            if (pow2it) {
                p0 = pix[t] << 1;         // scale == 2.0 exact; no clamp binds
                e  = dual ? 2 : 1;        // p1-p0 == 2 always
            } else {                      // it5: scale = tsrc*2^-11 exact
                const float scale = __fmul_rn(tsrc, 4.8828125e-4f);
                const float pf = (float)pix[t];
                p0 = min((int)rintf(__fmul_rn(pf, scale)), 4095);
                e = 1;
                if (dual) {
                    const int p1 = (int)rintf(__fmul_rn(pf + 1.0f, scale));
                    if (p1 - p0 >= 2) e = 2;
                }
            }
        }
        int incl = e;
        #pragma unroll
        for (int d = 1; d < 32; d <<= 1) {
            const int o = __shfl_up_sync(0xFFFFFFFFu, incl, d);
            if (lane >= d) incl += o;
        }
        if (lane == 31) wsum[wid] = incl;
        if (t == 0) sel[2] = winner ? 0 : 1;
        __syncthreads();                                     // B5

        const int extra = sel[2];
        int base2 = extra, total = extra;
        #pragma unroll
        for (int w2 = 0; w2 < 4; ++w2) {
            const int s = wsum[w2];
            if (w2 < wid) base2 += s;
            total += s;
        }
        const int pos = base2 + incl - e;                    // exclusive
        // prepended pixel-0: sc[0] already holds q.k[0] (slot-0 invariant)
        if (extra && t == 0) { pix[0] = 0; xs[0] = 0; }
        if (e >= 1 && pos < 128) {
            pix[pos] = p0;
            xs[pos]  = myx;               // bit-exact: x_child0 == x_parent
            sc[pos]  = sv;                // cached score
        }
        if (e == 2 && pos + 1 < 128) {
            const int pv = p0 + 1;
            pix[pos + 1] = pv;
            xs[pos + 1]  = pow2it
                ? min((int)rintf(__fmul_rn((float)pv, ratio_n)), 4095)
                : pv;                     // it5: ratio_n == 1 exactly
            wl[atomicAdd(&wlcnt, 1)] = pos + 1;   // uncached: gather next iter
        }
        const int Vn = min(total, 128);
        if (t >= Vn) { pix[t] = 0; xs[t] = 0; }
        __syncthreads();                                     // B6

        V  = Vn;
        ws = wsn;
    }

    // ==== it6 (ws==tsrc: ratio=1, scale=1, tks=64): top-64 membership ====
    {
        const int U = wlcnt;
        ((int2*)hist)[t] = make_int2(0, 0);
        if (t == 0) sel[0] = 0;
        #pragma unroll 1
        for (int base = 0; base < U; base += 32) {
            if (base + (wid << 2) < U) {
                const int  i0 = base + or8;
                const int  i1 = base + 16 + or8;
                const bool v0 = (i0 < U);
                const bool v1 = (i1 < U);
                const int  r0 = v0 ? wl[i0] : 0;
                const int  r1 = v1 ? wl[i1] : 0;
                float acc0 = 0.0f, acc1 = 0.0f;
                if (v0) {
                    const float4* kr = (const float4*)(kb + (size_t)xs[r0] * 64);
                    const float4 A = __ldg(kr + c8);
                    const float4 B = __ldg(kr + c8 + 8);
                    acc0  = A.x*qa.x + A.y*qa.y + A.z*qa.z + A.w*qa.w;
                    acc0 += B.x*qb.x + B.y*qb.y + B.z*qb.z + B.w*qb.w;
                }
                if (v1) {
                    const float4* kr = (const float4*)(kb + (size_t)xs[r1] * 64);
                    const float4 A = __ldg(kr + c8);
                    const float4 B = __ldg(kr + c8 + 8);
                    acc1  = A.x*qa.x + A.y*qa.y + A.z*qa.z + A.w*qa.w;
                    acc1 += B.x*qb.x + B.y*qb.y + B.z*qb.z + B.w*qb.w;
                }
                acc0 += __shfl_xor_sync(0xFFFFFFFFu, acc0, 1);
                acc1 += __shfl_xor_sync(0xFFFFFFFFu, acc1, 1);
                acc0 += __shfl_xor_sync(0xFFFFFFFFu, acc0, 2);
                acc1 += __shfl_xor_sync(0xFFFFFFFFu, acc1, 2);
                acc0 += __shfl_xor_sync(0xFFFFFFFFu, acc0, 4);
                acc1 += __shfl_xor_sync(0xFFFFFFFFu, acc1, 4);
                if (v0 && c8 == 0) sc[r0] = acc0;
                if (v1 && c8 == 0) sc[r1] = acc1;
            }
        }
        __syncthreads();                                     // C1

        const bool     valid  = (t < V);
        const float    sv     = valid ? sc[t] : FMINV;
        const unsigned u      = valid ? sortable_u(sv) : 0u;
        const int      bucket = valid ? lin_bucket(sv) : 0;
        if (valid) atomicAdd(&hist[bucket], 1);
        __syncthreads();                                     // C2

        int b1, m1;
        {
            const int  base4 = 248 - (lane << 3);
            const int4 A4 = *(const int4*)&hist[base4];
            const int4 B4 = *(const int4*)&hist[base4 + 4];
            const int  s  = A4.x+A4.y+A4.z+A4.w + B4.x+B4.y+B4.z+B4.w;
            int incl0 = s;
            #pragma unroll
            for (int d = 1; d < 32; d <<= 1) {
                const int o = __shfl_up_sync(0xFFFFFFFFu, incl0, d);
                if (lane >= d) incl0 += o;
            }
            int run = incl0 - s;
            const int hh[8] = {B4.w, B4.z, B4.y, B4.x, A4.w, A4.z, A4.y, A4.x};
            bool f1 = false;
            int b1l = 0, m1l = 0;
            #pragma unroll
            for (int j = 0; j < 8; ++j) {
                const int b = 255 - ((lane << 3) + j);
                const int h = hh[j];
                if (run < 64 && run + h >= 64) { b1l = b; m1l = run; f1 = true; }
                run += h;
            }
            const unsigned bb1 = __ballot_sync(0xFFFFFFFFu, f1);
            const int s1 = __ffs(bb1) - 1;
            b1 = __shfl_sync(0xFFFFFFFFu, b1l, s1);
            m1 = __shfl_sync(0xFFFFFFFFu, m1l, s1);
        }

        const bool c1 = valid && (bucket == b1);
        if (c1) cand1[atomicAdd(&sel[0], 1) & 63] = u;
        __syncthreads();                                     // C4

        bool member = false;
        if (valid) {
            if (bucket > b1) member = true;
            else if (c1) {
                const int C = min(sel[0], 64);
                int r = 0;
                for (int j = 0; j < C; ++j) r += (int)(cand1[j] > u);
                member = (r < 64 - m1);
            }
        }
        const bool  win = (t == 0) || member;   // slot 0 = pixel 0 pad
        const int   myp = pix[t];
        const float mys = sv;
        const unsigned wb = __ballot_sync(0xFFFFFFFFu, win);
        if (lane == 0) wsum[wid] = __popc(wb);
        __syncthreads();                                     // C5

        int wbase = 0, total = 0;
        #pragma unroll
        for (int w2 = 0; w2 < 4; ++w2) {
            const int s = wsum[w2];
            if (w2 < wid) wbase += s;
            total += s;
        }
        const int cnt = min(total, 64);
        const int pos = wbase + __popc(wb & ((1u << lane) - 1u));
        // slots pixel-ascending; keep the 64 smallest pixel values
        if (win && pos < 64) { pix[pos] = myp; sc[pos] = mys; }
        if (t >= cnt && t < 64) { pix[t] = 0; sc[t] = FMINV; }
        __syncthreads();                                     // C6
    }

    // ---- softmax via shfl reductions (warps 0-1 hold the 64 scores) ----
    if (t < 64) {
        float m = sc[t];
        #pragma unroll
        for (int d = 16; d >= 1; d >>= 1)
            m = fmaxf(m, __shfl_xor_sync(0xFFFFFFFFu, m, d));
        if (lane == 0) fsum[wid] = m;
    }
    __syncthreads();
    if (t < 64) {
        const float mx = fmaxf(fsum[0], fsum[1]);
        const float ex = __expf(sc[t] - mx);
        pr[t] = ex;
        float s = ex;
        #pragma unroll
        for (int d = 16; d >= 1; d >>= 1)
            s += __shfl_xor_sync(0xFFFFFFFFu, s, d);
        if (lane == 0) fsum[2 + wid] = s;
    }
    __syncthreads();
    const float denom = fsum[2] + fsum[3];

    // ---- AV gather: float4 warp-cooperative (warp owns 16 z-slots) ----
    const float* vb    = v + (size_t)n * (4096 * 64);
    const int    halfl = lane >> 4;       // 0/1: which z of the pair
    const int    col4  = lane & 15;       // float4 column chunk
    float4 acc4 = make_float4(0.0f, 0.0f, 0.0f, 0.0f);
    #pragma unroll
    for (int j = 0; j < 8; ++j) {
        const int   z  = (wid << 4) + (j << 1) + halfl;
        const float w  = pr[z];
        const float4 vv = __ldg((const float4*)(vb + (size_t)pix[z] * 64) + col4);
        acc4.x += w * vv.x;
        acc4.y += w * vv.y;
        acc4.z += w * vv.z;
        acc4.w += w * vv.w;
    }
    acc4.x += __shfl_xor_sync(0xFFFFFFFFu, acc4.x, 16);
    acc4.y += __shfl_xor_sync(0xFFFFFFFFu, acc4.y, 16);
    acc4.z += __shfl_xor_sync(0xFFFFFFFFu, acc4.z, 16);
    acc4.w += __shfl_xor_sync(0xFFFFFFFFu, acc4.w, 16);
    float4* red = (float4*)hist;          // reuse hist: 64 float4 = 1KB
    if (lane < 16) red[(wid << 4) + col4] = acc4;
    __syncthreads();
    if (t < 16) {
        const float4 s0 = red[t];
        const float4 s1 = red[16 + t];
        const float4 s2 = red[32 + t];
        const float4 s3 = red[48 + t];
        float4 o;
        o.x = (s0.x + s1.x + s2.x + s3.x) / denom;
        o.y = (s0.y + s1.y + s2.y + s3.y) / denom;
        o.z = (s0.z + s1.z + s2.z + s3.z) / denom;
        o.w = (s0.w + s1.w + s2.w + s3.w) / denom;
        ((float4*)out)[(size_t)row * 16 + t] = o;
    }
}

extern "C" void kernel_launch(void* const* d_in, const int* in_sizes, int n_in,
                              void* d_out, int out_size)
{
    const float* q = (const float*)d_in[0];   // (8, 512, 64)
    const float* k = (const float*)d_in[1];   // (8, 4096, 64)
    const float* v = (const float*)d_in[2];   // (8, 4096, 64)
    float* out = (float*)d_out;               // (8, 512, 64)
    (void)in_sizes; (void)n_in; (void)out_size;

    tree_attn_kernel<<<8 * 512, 128>>>(q, k, v, out);
}

// round 16
// speedup vs baseline: 1.2109x; 1.2109x over previous
#include <cuda_runtime.h>
#include <cstdint>

// TreeAttention: N=8, T_DST=512, T_SRC=4096, HID=64, K=64, W0=64,
// SCALE_UP=2, OVERSAMPLE=1.5. One CTA (128 threads) per (n, a) row.
//
// R14 structure (warp-0-only histogram scan; waiting warps' issue slots
// are absorbed by co-resident CTAs — R15 proved redundant scanning is a
// net loss) + LINEAR monotone bucketing (0.25-wide bins, clamp [0,255])
// so the crossing bucket holds only ~2-4 candidates for the exact
// in-bucket rank on full sortable keys.
//
// Score caching: child0's gather index equals its parent's BIT-EXACTLY,
// so child0 scores AND gather indices are copied at placement; only dual
// children (and the initial 64 rows) are gathered via worklist wl.
// Exact-arithmetic specializations: it0..4 scale==2 (integer emission,
// no clamps); ratio_n = tsrc*2^-k exact; it5 scale = tsrc*2^-11 exact,
// ratio_n == 1. Only the reference's ws/tsrc division remains.
//
// it6: final set = (top-64 ∪ {pixel 0}) truncated to 64 smallest pixels
// via ballot compaction. AV gather: float4 warp-cooperative.

#define NEGV  (-32000.0f)
#define FMINV (-1e30f)

__device__ __forceinline__ unsigned sortable_u(float f) {
    unsigned i = __float_as_uint(f);
    return i ^ ((unsigned)((int)i >> 31) | 0x80000000u);
}

__device__ __forceinline__ int lin_bucket(float s) {
    const int b = __float2int_rd(__fmaf_rn(s, 4.0f, 128.0f));
    return min(255, max(0, b));
}

__global__ __launch_bounds__(128, 10)
void tree_attn_kernel(const float* __restrict__ q,
                      const float* __restrict__ k,
                      const float* __restrict__ v,
                      float* __restrict__ out)
{
    const int row  = blockIdx.x;          // n*512 + a
    const int n    = row >> 9;
    const int a    = row & 511;
    const int t    = threadIdx.x;         // 0..127
    const int lane = t & 31;
    const int wid  = t >> 5;
    const int c8   = t & 7;               // chunk within row (8 threads/row)
    const int or8  = t >> 3;              // row slot (0..15)

    __shared__ __align__(16) float qs[64];
    __shared__ __align__(16) float sc[128];
    __shared__ __align__(16) float pr[64];
    __shared__ int      pix[128];
    __shared__ int      xs[128];          // gather indices
    __shared__ __align__(16) int hist[256];   // also reused as float4[64]
    __shared__ unsigned cand1[128];
    __shared__ unsigned cand2[128];
    __shared__ int      wl[128];          // uncached-slot worklist
    __shared__ int      wlcnt;
    __shared__ int      wsum[4];
    __shared__ float    fsum[4];
    __shared__ int      sel[7];           // bs1,m1,bs2,m2,cnt1,cnt2,extra

    const float  tsrc = (float)(3585 + a);        // T_SRC - T_DST + 1 + a
    const float* kb   = k + (size_t)n * (4096 * 64);

    if (t < 64) qs[t] = q[(size_t)row * 64 + t];
    {
        const float r0 = __fmul_rn(tsrc, 0.015625f);  // tsrc/64 exact
        const int   p  = (t < 96) ? t : 0;
        pix[t] = p;
        xs[t]  = min((int)rintf(__fmul_rn((float)p, r0)), 4095);
    }
    if (t < 64) wl[t] = t;                // initial rows all uncached
    if (t == 0) wlcnt = 64;
    __syncthreads();

    const float4 qa = ((const float4*)qs)[c8];
    const float4 qb = ((const float4*)qs)[c8 + 8];

    float ws = 64.0f;
    int   V  = 64;                        // valid prefix length (shared-state)

    #pragma unroll 1
    for (int it = 0; it < 6; ++it) {
        const int tks_max = (it == 0) ? 63 : 96;
        const int Zcur    = (it == 0) ? 96 : 128;

        // ---- A: gather ONLY uncached rows (worklist); zero hist ----
        const int U = wlcnt;              // read before any thread passes B1
        if (t >= V) sc[t] = NEGV;
        ((int2*)hist)[t] = make_int2(0, 0);
        if (t < 2) sel[4 + t] = 0;
        #pragma unroll 1
        for (int base = 0; base < U; base += 32) {
            if (base + (wid << 2) < U) {  // warp-uniform: this warp has rows
                const int  i0 = base + or8;
                const int  i1 = base + 16 + or8;
                const bool v0 = (i0 < U);
                const bool v1 = (i1 < U);
                const int  r0 = v0 ? wl[i0] : 0;
                const int  r1 = v1 ? wl[i1] : 0;
                float acc0 = 0.0f, acc1 = 0.0f;
                if (v0) {
                    const float4* kr = (const float4*)(kb + (size_t)xs[r0] * 64);
                    const float4 A = __ldg(kr + c8);
                    const float4 B = __ldg(kr + c8 + 8);
                    acc0  = A.x*qa.x + A.y*qa.y + A.z*qa.z + A.w*qa.w;
                    acc0 += B.x*qb.x + B.y*qb.y + B.z*qb.z + B.w*qb.w;
                }
                if (v1) {
                    const float4* kr = (const float4*)(kb + (size_t)xs[r1] * 64);
                    const float4 A = __ldg(kr + c8);
                    const float4 B = __ldg(kr + c8 + 8);
                    acc1  = A.x*qa.x + A.y*qa.y + A.z*qa.z + A.w*qa.w;
                    acc1 += B.x*qb.x + B.y*qb.y + B.z*qb.z + B.w*qb.w;
                }
                acc0 += __shfl_xor_sync(0xFFFFFFFFu, acc0, 1);
                acc1 += __shfl_xor_sync(0xFFFFFFFFu, acc1, 1);
                acc0 += __shfl_xor_sync(0xFFFFFFFFu, acc0, 2);
                acc1 += __shfl_xor_sync(0xFFFFFFFFu, acc1, 2);
                acc0 += __shfl_xor_sync(0xFFFFFFFFu, acc0, 4);
                acc1 += __shfl_xor_sync(0xFFFFFFFFu, acc1, 4);
                if (v0 && c8 == 0) sc[r0] = acc0;
                if (v1 && c8 == 0) sc[r1] = acc1;
            }
        }
        __syncthreads();                                     // B1
        if (t == 0) wlcnt = 0;            // safe: all reads of wl/U done

        // uniform params (single remaining fdiv: reference's ws/tsrc)
        float tkf = rintf(__fmul_rn(__fmul_rn(__fdiv_rn(ws, tsrc), 64.0f), 1.5f));
        tkf = fminf(fmaxf(tkf, 1.0f), fminf(ws - 1.0f, (float)(Zcur - 1)));
        const int  k1     = min((int)tkf, tks_max);          // dual top-k
        const int  k2     = tks_max;                         // winner top-k
        const bool needK2 = (V > tks_max);
        const bool pow2it = (it < 5);
        const float wsn   = pow2it ? __fmul_rn(ws, 2.0f) : tsrc;
        const float ratio_n = pow2it
            ? __fmul_rn(tsrc, __uint_as_float((unsigned)(120 - it) << 23))
            : 1.0f;

        const bool     valid  = (t < V);
        const float    sv     = sc[t];
        const int      myx    = xs[t];    // inherited by child0 (bit-exact)
        const unsigned u      = valid ? sortable_u(sv) : 0u;
        const int      bucket = valid ? lin_bucket(sv) : 0;
        if (valid) atomicAdd(&hist[bucket], 1);
        __syncthreads();                                     // B2

        // warp 0: descending suffix scan + crossing buckets
        if (wid == 0) {
            const int  base4 = 248 - (lane << 3);
            const int4 A4 = *(const int4*)&hist[base4];
            const int4 B4 = *(const int4*)&hist[base4 + 4];
            const int  s  = A4.x+A4.y+A4.z+A4.w + B4.x+B4.y+B4.z+B4.w;
            int incl0 = s;
            #pragma unroll
            for (int d = 1; d < 32; d <<= 1) {
                const int o = __shfl_up_sync(0xFFFFFFFFu, incl0, d);
                if (lane >= d) incl0 += o;
            }
            int run = incl0 - s;
            const int hh[8] = {B4.w, B4.z, B4.y, B4.x, A4.w, A4.z, A4.y, A4.x};
            #pragma unroll
            for (int j = 0; j < 8; ++j) {
                const int b = 255 - ((lane << 3) + j);
                const int h = hh[j];
                if (run < k1 && run + h >= k1) { sel[0] = b; sel[1] = run; }
                if (needK2 && run < k2 && run + h >= k2) { sel[2] = b; sel[3] = run; }
                run += h;
            }
        }
        __syncthreads();                                     // B3

        const bool c1 = valid && (bucket == sel[0]);
        if (c1) cand1[atomicAdd(&sel[4], 1)] = u;
        const bool c2 = needK2 && valid && (bucket == sel[2]);
        if (c2) cand2[atomicAdd(&sel[5], 1)] = u;
        __syncthreads();                                     // B4

        // ---- membership + monotone child emission ----
        bool winner = valid, dual = false;
        if (valid) {
            if (bucket > sel[0]) dual = true;
            else if (c1) {
                const int C = sel[4];
                int r = 0;
                for (int j = 0; j < C; ++j) r += (int)(cand1[j] > u);
                dual = (r < k1 - sel[1]);
            }
            if (needK2) {
                if (bucket > sel[2]) winner = true;
                else if (c2) {
                    const int C = sel[5];
                    int r = 0;
                    for (int j = 0; j < C; ++j) r += (int)(cand2[j] > u);
                    winner = (r < k2 - sel[3]);
                } else winner = false;
            }
        }
        int e = 0, p0 = 0;
        if (winner) {
            if (pow2it) {
                p0 = pix[t] << 1;         // scale == 2.0 exact; no clamp binds
                e  = dual ? 2 : 1;        // p1-p0 == 2 always
            } else {                      // it5: scale = tsrc*2^-11 exact
                const float scale = __fmul_rn(tsrc, 4.8828125e-4f);
                const float pf = (float)pix[t];
                p0 = min((int)rintf(__fmul_rn(pf, scale)), 4095);
                e = 1;
                if (dual) {
                    const int p1 = (int)rintf(__fmul_rn(pf + 1.0f, scale));
                    if (p1 - p0 >= 2) e = 2;
                }
            }
        }
        int incl = e;
        #pragma unroll
        for (int d = 1; d < 32; d <<= 1) {
            const int o = __shfl_up_sync(0xFFFFFFFFu, incl, d);
            if (lane >= d) incl += o;
        }
        if (lane == 31) wsum[wid] = incl;
        if (t == 0) sel[6] = winner ? 0 : 1;
        __syncthreads();                                     // B5

        const int extra = sel[6];
        int base2 = extra, total = extra;
        #pragma unroll
        for (int w2 = 0; w2 < 4; ++w2) {
            const int s = wsum[w2];
            if (w2 < wid) base2 += s;
            total += s;
        }
        const int pos = base2 + incl - e;                    // exclusive
        // prepended pixel-0: sc[0] already holds q.k[0] (slot-0 invariant)
        if (extra && t == 0) { pix[0] = 0; xs[0] = 0; }
        if (e >= 1 && pos < 128) {
            pix[pos] = p0;
            xs[pos]  = myx;               // bit-exact: x_child0 == x_parent
            sc[pos]  = sv;                // cached score
        }
        if (e == 2 && pos + 1 < 128) {
            const int pv = p0 + 1;
            pix[pos + 1] = pv;
            xs[pos + 1]  = pow2it
                ? min((int)rintf(__fmul_rn((float)pv, ratio_n)), 4095)
                : pv;                     // it5: ratio_n == 1 exactly
            wl[atomicAdd(&wlcnt, 1)] = pos + 1;   // uncached: gather next iter
        }
        const int Vn = min(total, 128);
        if (t >= Vn) { pix[t] = 0; xs[t] = 0; }
        __syncthreads();                                     // B6

        V  = Vn;
        ws = wsn;
    }

    // ==== it6 (ws==tsrc: ratio=1, scale=1, tks=64): top-64 membership ====
    {
        const int U = wlcnt;
        ((int2*)hist)[t] = make_int2(0, 0);
        if (t == 0) sel[4] = 0;
        #pragma unroll 1
        for (int base = 0; base < U; base += 32) {
            if (base + (wid << 2) < U) {
                const int  i0 = base + or8;
                const int  i1 = base + 16 + or8;
                const bool v0 = (i0 < U);
                const bool v1 = (i1 < U);
                const int  r0 = v0 ? wl[i0] : 0;
                const int  r1 = v1 ? wl[i1] : 0;
                float acc0 = 0.0f, acc1 = 0.0f;
                if (v0) {
                    const float4* kr = (const float4*)(kb + (size_t)xs[r0] * 64);
                    const float4 A = __ldg(kr + c8);
                    const float4 B = __ldg(kr + c8 + 8);
                    acc0  = A.x*qa.x + A.y*qa.y + A.z*qa.z + A.w*qa.w;
                    acc0 += B.x*qb.x + B.y*qb.y + B.z*qb.z + B.w*qb.w;
                }
                if (v1) {
                    const float4* kr = (const float4*)(kb + (size_t)xs[r1] * 64);
                    const float4 A = __ldg(kr + c8);
                    const float4 B = __ldg(kr + c8 + 8);
                    acc1  = A.x*qa.x + A.y*qa.y + A.z*qa.z + A.w*qa.w;
                    acc1 += B.x*qb.x + B.y*qb.y + B.z*qb.z + B.w*qb.w;
                }
                acc0 += __shfl_xor_sync(0xFFFFFFFFu, acc0, 1);
                acc1 += __shfl_xor_sync(0xFFFFFFFFu, acc1, 1);
                acc0 += __shfl_xor_sync(0xFFFFFFFFu, acc0, 2);
                acc1 += __shfl_xor_sync(0xFFFFFFFFu, acc1, 2);
                acc0 += __shfl_xor_sync(0xFFFFFFFFu, acc0, 4);
                acc1 += __shfl_xor_sync(0xFFFFFFFFu, acc1, 4);
                if (v0 && c8 == 0) sc[r0] = acc0;
                if (v1 && c8 == 0) sc[r1] = acc1;
            }
        }
        __syncthreads();                                     // C1

        const bool     valid  = (t < V);
        const float    sv     = valid ? sc[t] : FMINV;
        const unsigned u      = valid ? sortable_u(sv) : 0u;
        const int      bucket = valid ? lin_bucket(sv) : 0;
        if (valid) atomicAdd(&hist[bucket], 1);
        __syncthreads();                                     // C2

        if (wid == 0) {
            const int  base4 = 248 - (lane << 3);
            const int4 A4 = *(const int4*)&hist[base4];
            const int4 B4 = *(const int4*)&hist[base4 + 4];
            const int  s  = A4.x+A4.y+A4.z+A4.w + B4.x+B4.y+B4.z+B4.w;
            int incl0 = s;
            #pragma unroll
            for (int d = 1; d < 32; d <<= 1) {
                const int o = __shfl_up_sync(0xFFFFFFFFu, incl0, d);
                if (lane >= d) incl0 += o;
            }
            int run = incl0 - s;
            const int hh[8] = {B4.w, B4.z, B4.y, B4.x, A4.w, A4.z, A4.y, A4.x};
            #pragma unroll
            for (int j = 0; j < 8; ++j) {
                const int b = 255 - ((lane << 3) + j);
                const int h = hh[j];
                if (run < 64 && run + h >= 64) { sel[0] = b; sel[1] = run; }
                run += h;
            }
        }
        __syncthreads();                                     // C3

        const bool c1 = valid && (bucket == sel[0]);
        if (c1) cand1[atomicAdd(&sel[4], 1)] = u;
        __syncthreads();                                     // C4

        bool member = false;
        if (valid) {
            if (bucket > sel[0]) member = true;
            else if (c1) {
                const int C = sel[4];
                int r = 0;
                for (int j = 0; j < C; ++j) r += (int)(cand1[j] > u);
                member = (r < 64 - sel[1]);
            }
        }
        const bool  win = (t == 0) || member;   // slot 0 = pixel 0 pad
        const int   myp = pix[t];
        const float mys = sv;
        const unsigned wb = __ballot_sync(0xFFFFFFFFu, win);
        if (lane == 0) wsum[wid] = __popc(wb);
        __syncthreads();                                     // C5

        int wbase = 0, total = 0;
        #pragma unroll
        for (int w2 = 0; w2 < 4; ++w2) {
            const int s = wsum[w2];
            if (w2 < wid) wbase += s;
            total += s;
        }
        const int cnt = min(total, 64);
        const int pos = wbase + __popc(wb & ((1u << lane) - 1u));
        // slots pixel-ascending; keep the 64 smallest pixel values
        if (win && pos < 64) { pix[pos] = myp; sc[pos] = mys; }
        if (t >= cnt && t < 64) { pix[t] = 0; sc[t] = FMINV; }
        __syncthreads();                                     // C6
    }

    // ---- softmax via shfl reductions (warps 0-1 hold the 64 scores) ----
    if (t < 64) {
        float m = sc[t];
        #pragma unroll
        for (int d = 16; d >= 1; d >>= 1)
            m = fmaxf(m, __shfl_xor_sync(0xFFFFFFFFu, m, d));
        if (lane == 0) fsum[wid] = m;
    }
    __syncthreads();
    if (t < 64) {
        const float mx = fmaxf(fsum[0], fsum[1]);
        const float ex = __expf(sc[t] - mx);
        pr[t] = ex;
        float s = ex;
        #pragma unroll
        for (int d = 16; d >= 1; d >>= 1)
            s += __shfl_xor_sync(0xFFFFFFFFu, s, d);
        if (lane == 0) fsum[2 + wid] = s;
    }
    __syncthreads();
    const float denom = fsum[2] + fsum[3];

    // ---- AV gather: float4 warp-cooperative (warp owns 16 z-slots) ----
    const float* vb    = v + (size_t)n * (4096 * 64);
    const int    halfl = lane >> 4;       // 0/1: which z of the pair
    const int    col4  = lane & 15;       // float4 column chunk
    float4 acc4 = make_float4(0.0f, 0.0f, 0.0f, 0.0f);
    #pragma unroll
    for (int j = 0; j < 8; ++j) {
        const int   z  = (wid << 4) + (j << 1) + halfl;
        const float w  = pr[z];
        const float4 vv = __ldg((const float4*)(vb + (size_t)pix[z] * 64) + col4);
        acc4.x += w * vv.x;
        acc4.y += w * vv.y;
        acc4.z += w * vv.z;
        acc4.w += w * vv.w;
    }
    acc4.x += __shfl_xor_sync(0xFFFFFFFFu, acc4.x, 16);
    acc4.y += __shfl_xor_sync(0xFFFFFFFFu, acc4.y, 16);
    acc4.z += __shfl_xor_sync(0xFFFFFFFFu, acc4.z, 16);
    acc4.w += __shfl_xor_sync(0xFFFFFFFFu, acc4.w, 16);
    float4* red = (float4*)hist;          // reuse hist: 64 float4 = 1KB
    if (lane < 16) red[(wid << 4) + col4] = acc4;
    __syncthreads();
    if (t < 16) {
        const float4 s0 = red[t];
        const float4 s1 = red[16 + t];
        const float4 s2 = red[32 + t];
        const float4 s3 = red[48 + t];
        float4 o;
        o.x = (s0.x + s1.x + s2.x + s3.x) / denom;
        o.y = (s0.y + s1.y + s2.y + s3.y) / denom;
        o.z = (s0.z + s1.z + s2.z + s3.z) / denom;
        o.w = (s0.w + s1.w + s2.w + s3.w) / denom;
        ((float4*)out)[(size_t)row * 16 + t] = o;
    }
}

extern "C" void kernel_launch(void* const* d_in, const int* in_sizes, int n_in,
                              void* d_out, int out_size)
{
    const float* q = (const float*)d_in[0];   // (8, 512, 64)
    const float* k = (const float*)d_in[1];   // (8, 4096, 64)
    const float* v = (const float*)d_in[2];   // (8, 4096, 64)
    float* out = (float*)d_out;               // (8, 512, 64)
    (void)in_sizes; (void)n_in; (void)out_size;

    tree_attn_kernel<<<8 * 512, 128>>>(q, k, v, out);
}